// round 4
// baseline (speedup 1.0000x reference)
#include <cuda_runtime.h>
#include <cuda_bf16.h>
#include <math.h>

#define NN    100000
#define NPAD  100096      // 391 * 256
#define EE    1250000
#define RR    16
#define DD    64
#define SCANB (NPAD / 256)   // 391

// ---------------- static device scratch (no allocs allowed) ----------------
__device__ __nv_bfloat16 g_egoB[NPAD * DD];              // ego bf16, zero-padded
__device__ __nv_bfloat16 g_Wbf[RR * DD * DD];            // Wt[r][j][d] = W[r][d][j]
__device__ __nv_bfloat16 g_Tall[(size_t)NPAD * RR * DD]; // [node][rel][64] bf16
__device__ int2          g_pair[EE];                     // CSR-ordered (tail, etype)
__device__ int           g_rowstart[NN + 2];
__device__ int           g_cursor[NN];
__device__ int           g_cnt[NN];
__device__ int           g_bsum[SCANB + 1];
__device__ int           g_boff[SCANB + 1];

// ---------------- init ----------------
__global__ void k_init(const float* __restrict__ ego, const float* __restrict__ W, int N) {
    int idx = blockIdx.x * blockDim.x + threadIdx.x;
    if (idx < NPAD * DD)
        g_egoB[idx] = __float2bfloat16(idx < N * DD ? ego[idx] : 0.0f);
    if (idx < RR * DD * DD) {
        int r = idx >> 12, rem = idx & 4095;
        int j = rem >> 6, d = rem & 63;
        g_Wbf[idx] = __float2bfloat16(W[(r << 12) + d * DD + j]);
    }
    if (idx < N) g_cnt[idx] = 0;
}

// ---------------- CSR build ----------------
__global__ void k_hist(const int* __restrict__ head, int E) {
    int e = blockIdx.x * blockDim.x + threadIdx.x;
    if (e < E) atomicAdd(&g_cnt[head[e]], 1);
}

__global__ void k_scan1(int N) {
    __shared__ int sh[8];
    int b = blockIdx.x, t = threadIdx.x;
    int i = b * 256 + t;
    int v = (i < N) ? g_cnt[i] : 0;
    int x = v;
    #pragma unroll
    for (int o = 16; o; o >>= 1) x += __shfl_xor_sync(0xffffffffu, x, o);
    if ((t & 31) == 0) sh[t >> 5] = x;
    __syncthreads();
    if (t == 0) {
        int s = 0;
        #pragma unroll
        for (int q = 0; q < 8; q++) s += sh[q];
        g_bsum[b] = s;
    }
}

__global__ void k_scan2() {
    __shared__ int wsum[16];
    int t = threadIdx.x;
    int v = (t < SCANB) ? g_bsum[t] : 0;
    int x = v;
    #pragma unroll
    for (int o = 1; o < 32; o <<= 1) {
        int y = __shfl_up_sync(0xffffffffu, x, o);
        if ((t & 31) >= o) x += y;
    }
    if ((t & 31) == 31) wsum[t >> 5] = x;
    __syncthreads();
    if (t < 16) {
        int s = wsum[t], xs = s;
        #pragma unroll
        for (int o = 1; o < 16; o <<= 1) {
            int y = __shfl_up_sync(0xffffu, xs, o);
            if (t >= o) xs += y;
        }
        wsum[t] = xs - s;
    }
    __syncthreads();
    if (t < SCANB) g_boff[t] = (x - v) + wsum[t >> 5];
}

__global__ void k_scan3(int N, int E) {
    __shared__ int wsum[8];
    int b = blockIdx.x, t = threadIdx.x;
    int i = b * 256 + t;
    int v = (i < N) ? g_cnt[i] : 0;
    int x = v;
    #pragma unroll
    for (int o = 1; o < 32; o <<= 1) {
        int y = __shfl_up_sync(0xffffffffu, x, o);
        if ((t & 31) >= o) x += y;
    }
    if ((t & 31) == 31) wsum[t >> 5] = x;
    __syncthreads();
    if (t < 8) {
        int s = wsum[t], xs = s;
        #pragma unroll
        for (int o = 1; o < 8; o <<= 1) {
            int y = __shfl_up_sync(0xffu, xs, o);
            if (t >= o) xs += y;
        }
        wsum[t] = xs - s;
    }
    __syncthreads();
    int excl = (x - v) + wsum[t >> 5] + g_boff[b];
    if (i <= N) g_rowstart[i] = (i == N) ? E : excl;
    if (i < N)  g_cursor[i] = excl;
}

__global__ void k_fill(const int* __restrict__ head, const int* __restrict__ tail,
                       const int* __restrict__ etype, int E) {
    int e = blockIdx.x * blockDim.x + threadIdx.x;
    if (e < E) {
        int pos = atomicAdd(&g_cursor[head[e]], 1);
        g_pair[pos] = make_int2(tail[e], etype[e]);
    }
}

// ---------------- GEMM: T_all[n][r] = egoB[n] @ W[r], bf16 out ----------------
__global__ void __launch_bounds__(256) k_gemm() {
    __shared__ __nv_bfloat16 sW[DD * DD];
    int r = blockIdx.y;
    int warp = threadIdx.x >> 5, lane = threadIdx.x & 31;
    int g = lane >> 2, t = lane & 3;
    int base = blockIdx.x * 256 + warp * 32;

    const float4* src = (const float4*)(g_Wbf + (r << 12));
    float4* dst = (float4*)sW;
    for (int i = threadIdx.x; i < DD * DD / 8; i += 256) dst[i] = src[i];
    __syncthreads();

    float acc[2][8][4];
    #pragma unroll
    for (int i = 0; i < 2; i++)
        #pragma unroll
        for (int j = 0; j < 8; j++)
            #pragma unroll
            for (int q = 0; q < 4; q++) acc[i][j][q] = 0.0f;

    #pragma unroll
    for (int ks = 0; ks < 4; ks++) {
        int k0 = ks * 16;
        unsigned a[2][4];
        #pragma unroll
        for (int mt = 0; mt < 2; mt++) {
            int r0 = base + mt * 16;
            const unsigned* p0 = (const unsigned*)(g_egoB + (size_t)(r0 + g) * DD + k0 + 2 * t);
            const unsigned* p1 = (const unsigned*)(g_egoB + (size_t)(r0 + g + 8) * DD + k0 + 2 * t);
            a[mt][0] = p0[0];
            a[mt][1] = p1[0];
            a[mt][2] = p0[4];
            a[mt][3] = p1[4];
        }
        #pragma unroll
        for (int nt = 0; nt < 8; nt++) {
            const unsigned* q = (const unsigned*)(sW + (nt * 8 + g) * DD + k0 + 2 * t);
            unsigned b0 = q[0], b1 = q[4];
            #pragma unroll
            for (int mt = 0; mt < 2; mt++) {
                asm volatile(
                    "mma.sync.aligned.m16n8k16.row.col.f32.bf16.bf16.f32 "
                    "{%0,%1,%2,%3}, {%4,%5,%6,%7}, {%8,%9}, {%0,%1,%2,%3};"
                    : "+f"(acc[mt][nt][0]), "+f"(acc[mt][nt][1]),
                      "+f"(acc[mt][nt][2]), "+f"(acc[mt][nt][3])
                    : "r"(a[mt][0]), "r"(a[mt][1]), "r"(a[mt][2]), "r"(a[mt][3]),
                      "r"(b0), "r"(b1));
            }
        }
    }
    // store to [node][rel][64] layout
    #pragma unroll
    for (int mt = 0; mt < 2; mt++)
        #pragma unroll
        for (int nt = 0; nt < 8; nt++) {
            int row0 = base + mt * 16 + g;
            int col = nt * 8 + 2 * t;
            __nv_bfloat162 h0 = __floats2bfloat162_rn(acc[mt][nt][0], acc[mt][nt][1]);
            __nv_bfloat162 h1 = __floats2bfloat162_rn(acc[mt][nt][2], acc[mt][nt][3]);
            *(unsigned*)(g_Tall + ((size_t)row0 * RR + r) * DD + col)       = *(unsigned*)&h0;
            *(unsigned*)(g_Tall + ((size_t)(row0 + 8) * RR + r) * DD + col) = *(unsigned*)&h1;
        }
}

// ---------------- fused pass: warp per node, 8 lanes per edge ----------------
__global__ void __launch_bounds__(256) k_fused(const float* __restrict__ ego,
                                               float* __restrict__ out, int N) {
    int w = (blockIdx.x * blockDim.x + threadIdx.x) >> 5;
    int lane = threadIdx.x & 31;
    if (w >= N) return;
    int g = lane >> 3, q = lane & 7;
    unsigned gmask = 0xFFu << (g * 8);
    int s = g_rowstart[w], en = g_rowstart[w + 1];
    int cnt = en - s;

    const __nv_bfloat16* Tn = g_Tall + (size_t)w * RR * DD;  // node's 16 rel rows (2KB)
    float4 ax0 = make_float4(0.f, 0.f, 0.f, 0.f);
    float4 ax1 = make_float4(0.f, 0.f, 0.f, 0.f);
    float den = 0.0f;

    #pragma unroll 2
    for (int idx = s + g; idx < en; idx += 4) {
        int2 pe = g_pair[idx];
        // T[r] dims q*8..q*8+7 : 16B
        uint4 tv = *(const uint4*)(Tn + pe.y * DD + q * 8);
        const float4* vp = (const float4*)(ego + (size_t)pe.x * DD + q * 8);
        float4 v0 = vp[0];
        float4 v1 = vp[1];
        float2 a0 = __bfloat1622float2(*(__nv_bfloat162*)&tv.x);
        float2 a1 = __bfloat1622float2(*(__nv_bfloat162*)&tv.y);
        float2 a2 = __bfloat1622float2(*(__nv_bfloat162*)&tv.z);
        float2 a3 = __bfloat1622float2(*(__nv_bfloat162*)&tv.w);
        float d = a0.x * v0.x + a0.y * v0.y;
        d = fmaf(a1.x, v0.z, d);  d = fmaf(a1.y, v0.w, d);
        d = fmaf(a2.x, v1.x, d);  d = fmaf(a2.y, v1.y, d);
        d = fmaf(a3.x, v1.z, d);  d = fmaf(a3.y, v1.w, d);
        // reduce over the 8 lanes of this group
        d += __shfl_xor_sync(gmask, d, 1);
        d += __shfl_xor_sync(gmask, d, 2);
        d += __shfl_xor_sync(gmask, d, 4);
        float sc = d < 0.0f ? 0.01f * d : d;
        float e = __expf(sc);
        den += e;
        ax0.x = fmaf(e, v0.x, ax0.x); ax0.y = fmaf(e, v0.y, ax0.y);
        ax0.z = fmaf(e, v0.z, ax0.z); ax0.w = fmaf(e, v0.w, ax0.w);
        ax1.x = fmaf(e, v1.x, ax1.x); ax1.y = fmaf(e, v1.y, ax1.y);
        ax1.z = fmaf(e, v1.z, ax1.z); ax1.w = fmaf(e, v1.w, ax1.w);
    }
    __syncwarp();
    // combine the 4 groups (lanes with same q hold the same dims)
    #pragma unroll
    for (int o = 8; o <= 16; o <<= 1) {
        ax0.x += __shfl_xor_sync(0xffffffffu, ax0.x, o);
        ax0.y += __shfl_xor_sync(0xffffffffu, ax0.y, o);
        ax0.z += __shfl_xor_sync(0xffffffffu, ax0.z, o);
        ax0.w += __shfl_xor_sync(0xffffffffu, ax0.w, o);
        ax1.x += __shfl_xor_sync(0xffffffffu, ax1.x, o);
        ax1.y += __shfl_xor_sync(0xffffffffu, ax1.y, o);
        ax1.z += __shfl_xor_sync(0xffffffffu, ax1.z, o);
        ax1.w += __shfl_xor_sync(0xffffffffu, ax1.w, o);
        den   += __shfl_xor_sync(0xffffffffu, den, o);
    }
    if (g == 0) {
        float sc = cnt > 0 ? 1.0f / (den * (float)cnt) : 0.0f;
        float4* op = (float4*)(out + (size_t)w * DD + q * 8);
        op[0] = make_float4(ax0.x * sc, ax0.y * sc, ax0.z * sc, ax0.w * sc);
        op[1] = make_float4(ax1.x * sc, ax1.y * sc, ax1.z * sc, ax1.w * sc);
    }
}

// ---------------- launch ----------------
extern "C" void kernel_launch(void* const* d_in, const int* in_sizes, int n_in,
                              void* d_out, int out_size) {
    const float* ego   = (const float*)d_in[0];
    const float* W     = (const float*)d_in[1];
    const int*   eidx  = (const int*)d_in[2];
    const int*   etype = (const int*)d_in[3];
    int N = in_sizes[0] / DD;
    int E = in_sizes[3];
    const int* head = eidx;
    const int* tail = eidx + E;
    float* out = (float*)d_out;

    k_init<<<(NPAD * DD + 255) / 256, 256>>>(ego, W, N);
    k_hist<<<(E + 255) / 256, 256>>>(head, E);
    k_scan1<<<SCANB, 256>>>(N);
    k_scan2<<<1, 512>>>();
    k_scan3<<<SCANB, 256>>>(N, E);
    k_fill<<<(E + 255) / 256, 256>>>(head, tail, etype, E);
    k_gemm<<<dim3(NPAD / 256, RR), 256>>>();
    k_fused<<<(N * 32 + 255) / 256, 256>>>(ego, out, N);
}